// round 1
// baseline (speedup 1.0000x reference)
#include <cuda_runtime.h>
#include <cstdint>

// Problem constants (B=2, C=1, D=128, H=256, W=256)
#define NVOL   2           // B*C volumes
#define DD     128
#define HH     256
#define WW     256
#define NB     (NVOL*DD*HH*WW)      // 16,777,216 voxels
#define WPR    (WW/32)              // 8 packed words per row
#define NWORDS (NVOL*DD*HH*WPR)     // 524,288 words (2 MB)
#define PW     10.0f

// Scratch (allocation-free: __device__ globals)
__device__ unsigned int g_mask[NWORDS];
__device__ unsigned int g_tmp[NWORDS];
__device__ double g_acc;

// ---------------------------------------------------------------------------
// Kernel 1: binary mask (0 < t < 1) packed 32 voxels/word via ballot.
// Also zeroes the accumulator (runs strictly before the loss kernel).
// ---------------------------------------------------------------------------
__global__ void mask_pack_kernel(const float* __restrict__ tgt) {
    int t = blockIdx.x * blockDim.x + threadIdx.x;
    if (t == 0) g_acc = 0.0;
    float v = tgt[t];
    // clip(t,0,1) then zero where ==1  =>  nonzero iff 0 < t < 1
    bool m = (v > 0.0f) && (v < 1.0f);
    unsigned bal = __ballot_sync(0xFFFFFFFFu, m);
    if ((threadIdx.x & 31) == 0) g_mask[t >> 5] = bal;
}

// horizontal (x) dilation by +-3 bits across word boundaries
__device__ __forceinline__ unsigned hdil3(unsigned prev, unsigned cur, unsigned next) {
    unsigned r = cur;
    r |= (cur << 1) | (prev >> 31);
    r |= (cur << 2) | (prev >> 30);
    r |= (cur << 3) | (prev >> 29);
    r |= (cur >> 1) | (next << 31);
    r |= (cur >> 2) | (next << 30);
    r |= (cur >> 3) | (next << 29);
    return r;
}

// ---------------------------------------------------------------------------
// Kernel 2: x+y dilation. g_mask -> g_tmp. One thread per output word.
// ---------------------------------------------------------------------------
__global__ void dilate_xy_kernel() {
    int idx = blockIdx.x * blockDim.x + threadIdx.x;   // word index
    if (idx >= NWORDS) return;
    int wx  = idx & (WPR - 1);
    int row = idx >> 3;            // global row id: (v*DD+z)*HH + y
    int y   = row & (HH - 1);
    int vz  = row >> 8;            // v*DD + z  (0..255)

    unsigned acc = 0u;
    #pragma unroll
    for (int dy = -3; dy <= 3; ++dy) {
        int yy = y + dy;
        if (yy < 0 || yy >= HH) continue;
        int base = ((vz << 8) + yy) << 3;   // row base word index
        unsigned cur  = g_mask[base + wx];
        unsigned prev = (wx > 0)       ? g_mask[base + wx - 1] : 0u;
        unsigned next = (wx < WPR - 1) ? g_mask[base + wx + 1] : 0u;
        acc |= hdil3(prev, cur, next);
    }
    g_tmp[idx] = acc;
}

// ---------------------------------------------------------------------------
// Kernel 3: z dilation. g_tmp -> g_mask. Volumes independent in z.
// ---------------------------------------------------------------------------
__global__ void dilate_z_kernel() {
    int idx = blockIdx.x * blockDim.x + threadIdx.x;
    if (idx >= NWORDS) return;
    int wxy = idx & (HH * WPR - 1);   // (y*WPR + wx) within a z-slice
    int vz  = idx >> 11;              // v*DD + z
    int z   = vz & (DD - 1);
    int v   = vz >> 7;

    unsigned acc = 0u;
    #pragma unroll
    for (int dz = -3; dz <= 3; ++dz) {
        int zz = z + dz;
        if (zz < 0 || zz >= DD) continue;
        acc |= g_tmp[(((v << 7) + zz) << 11) + wxy];
    }
    g_mask[idx] = acc;
}

// ---------------------------------------------------------------------------
// Kernel 4: fused weighted-L1 sum. Vectorized float4, mask from L2.
// ---------------------------------------------------------------------------
__global__ void loss_kernel(const float4* __restrict__ inp,
                            const float4* __restrict__ tgt) {
    const int n4     = NB / 4;
    const int stride = gridDim.x * blockDim.x;
    float lsum = 0.0f;

    for (int i = blockIdx.x * blockDim.x + threadIdx.x; i < n4; i += stride) {
        float4 a = inp[i];
        float4 b = tgt[i];
        unsigned word = g_mask[i >> 3];            // 8 float4s per word
        unsigned bits = word >> ((i & 7) << 2);    // 4 bits for this quad
        float w0 = 1.0f + PW * (float)((bits >> 0) & 1u);
        float w1 = 1.0f + PW * (float)((bits >> 1) & 1u);
        float w2 = 1.0f + PW * (float)((bits >> 2) & 1u);
        float w3 = 1.0f + PW * (float)((bits >> 3) & 1u);
        lsum += fabsf(b.x - a.x) * w0;
        lsum += fabsf(b.y - a.y) * w1;
        lsum += fabsf(b.z - a.z) * w2;
        lsum += fabsf(b.w - a.w) * w3;
    }

    // warp reduce (float)
    #pragma unroll
    for (int off = 16; off > 0; off >>= 1)
        lsum += __shfl_down_sync(0xFFFFFFFFu, lsum, off);

    __shared__ float warp_sums[32];
    int lane = threadIdx.x & 31;
    int wid  = threadIdx.x >> 5;
    if (lane == 0) warp_sums[wid] = lsum;
    __syncthreads();

    if (wid == 0) {
        int nwarps = blockDim.x >> 5;
        float s = (lane < nwarps) ? warp_sums[lane] : 0.0f;
        #pragma unroll
        for (int off = 16; off > 0; off >>= 1)
            s += __shfl_down_sync(0xFFFFFFFFu, s, off);
        if (lane == 0) atomicAdd(&g_acc, (double)s);
    }
}

// ---------------------------------------------------------------------------
// Kernel 5: finalize mean
// ---------------------------------------------------------------------------
__global__ void finalize_kernel(float* __restrict__ out) {
    out[0] = (float)(g_acc / (double)NB);
}

extern "C" void kernel_launch(void* const* d_in, const int* in_sizes, int n_in,
                              void* d_out, int out_size) {
    const float* inp = (const float*)d_in[0];
    const float* tgt = (const float*)d_in[1];
    float* out = (float*)d_out;

    mask_pack_kernel<<<NB / 256, 256>>>(tgt);
    dilate_xy_kernel<<<NWORDS / 256, 256>>>();
    dilate_z_kernel<<<NWORDS / 256, 256>>>();
    loss_kernel<<<2048, 256>>>((const float4*)inp, (const float4*)tgt);
    finalize_kernel<<<1, 1>>>(out);
}

// round 2
// speedup vs baseline: 1.6802x; 1.6802x over previous
#include <cuda_runtime.h>
#include <cstdint>

// Problem constants (B=2, C=1, D=128, H=256, W=256)
#define NVOL   2
#define DD     128
#define HH     256
#define WW     256
#define NB     (NVOL*DD*HH*WW)      // 16,777,216 voxels
#define WPR    (WW/32)              // 8 packed words per row
#define NWORDS (NVOL*DD*HH*WPR)     // 524,288 words (2 MB)
#define PW     10.0f

#define LOSS_BLOCKS  2048
#define LOSS_THREADS 256
#define LOSS_TOTAL   (LOSS_BLOCKS*LOSS_THREADS)   // 524,288 threads
// n4 = NB/4 = 4,194,304 quads -> exactly 8 quads per thread

__device__ unsigned int g_mask[NWORDS];
__device__ unsigned int g_tmp[NWORDS];
__device__ double g_acc;
__device__ unsigned int g_bcount;

// ---------------------------------------------------------------------------
// Kernel 1: binary mask (0 < t < 1), float4 loads, shfl-tree packing.
// ---------------------------------------------------------------------------
__global__ void mask_pack_kernel(const float* __restrict__ tgt) {
    int q = blockIdx.x * blockDim.x + threadIdx.x;    // quad index
    if (q == 0) { g_acc = 0.0; g_bcount = 0u; }
    float4 v = __ldcs(((const float4*)tgt) + q);

    unsigned nib =
        (unsigned)(v.x > 0.0f && v.x < 1.0f)
      | ((unsigned)(v.y > 0.0f && v.y < 1.0f) << 1)
      | ((unsigned)(v.z > 0.0f && v.z < 1.0f) << 2)
      | ((unsigned)(v.w > 0.0f && v.w < 1.0f) << 3);

    // Assemble 32-bit words from 8 nibbles via shfl tree.
    unsigned a = nib | (__shfl_down_sync(0xFFFFFFFFu, nib, 1) << 4);
    unsigned b = a   | (__shfl_down_sync(0xFFFFFFFFu, a,   2) << 8);
    unsigned w = b   | (__shfl_down_sync(0xFFFFFFFFu, b,   4) << 16);

    if ((threadIdx.x & 7) == 0) g_mask[q >> 3] = w;
}

// horizontal (x) dilation by +-3 bits across word boundaries
__device__ __forceinline__ unsigned hdil3(unsigned prev, unsigned cur, unsigned next) {
    unsigned r = cur;
    r |= (cur << 1) | (prev >> 31);
    r |= (cur << 2) | (prev >> 30);
    r |= (cur << 3) | (prev >> 29);
    r |= (cur >> 1) | (next << 31);
    r |= (cur >> 2) | (next << 30);
    r |= (cur >> 3) | (next << 29);
    return r;
}

// ---------------------------------------------------------------------------
// Kernel 2: x+y dilation, 4 y-outputs per thread (register row window).
// ---------------------------------------------------------------------------
__global__ void dilate_xy_kernel() {
    int t = blockIdx.x * blockDim.x + threadIdx.x;    // 131072 threads
    int wx = t & 7;
    int yg = (t >> 3) & 63;
    int vz = t >> 9;                                  // v*DD+z, 0..255
    int rowbase = vz << 11;                           // vz * 256 rows * 8 words
    int y0 = yg << 2;

    unsigned hr[10];
    #pragma unroll
    for (int r = 0; r < 10; ++r) {
        int yy = y0 - 3 + r;
        if (yy < 0 || yy >= HH) { hr[r] = 0u; continue; }
        int base = rowbase + (yy << 3);
        unsigned cur  = g_mask[base + wx];
        unsigned prev = (wx > 0) ? g_mask[base + wx - 1] : 0u;
        unsigned next = (wx < 7) ? g_mask[base + wx + 1] : 0u;
        hr[r] = hdil3(prev, cur, next);
    }
    #pragma unroll
    for (int k = 0; k < 4; ++k) {
        unsigned acc = hr[k];
        #pragma unroll
        for (int r = 1; r < 7; ++r) acc |= hr[k + r];
        g_tmp[rowbase + ((y0 + k) << 3) + wx] = acc;
    }
}

// ---------------------------------------------------------------------------
// Kernel 3: z dilation, 4 z-outputs per thread. g_tmp -> g_mask.
// ---------------------------------------------------------------------------
__global__ void dilate_z_kernel() {
    int t = blockIdx.x * blockDim.x + threadIdx.x;    // 131072 threads
    int wxy = t & 2047;                               // word within z-slice
    int zg  = (t >> 11) & 31;
    int v   = t >> 16;
    int z0  = zg << 2;

    unsigned c[10];
    #pragma unroll
    for (int r = 0; r < 10; ++r) {
        int zz = z0 - 3 + r;
        c[r] = (zz >= 0 && zz < DD) ? g_tmp[(((v << 7) + zz) << 11) + wxy] : 0u;
    }
    #pragma unroll
    for (int k = 0; k < 4; ++k) {
        unsigned acc = c[k];
        #pragma unroll
        for (int r = 1; r < 7; ++r) acc |= c[k + r];
        g_mask[(((v << 7) + (z0 + k)) << 11) + wxy] = acc;
    }
}

// ---------------------------------------------------------------------------
// Kernel 4: fused weighted-L1 sum + mean finalize (last-block writes out).
// Each thread handles exactly 8 quads at stride LOSS_TOTAL.
// ---------------------------------------------------------------------------
__global__ void __launch_bounds__(LOSS_THREADS) loss_kernel(
        const float4* __restrict__ inp,
        const float4* __restrict__ tgt,
        float* __restrict__ out) {
    int tid = blockIdx.x * blockDim.x + threadIdx.x;
    // stride is a multiple of 8 -> (i & 7) is loop-invariant
    const int shift = (tid & 7) << 2;
    float lsum = 0.0f;

    #pragma unroll
    for (int half = 0; half < 2; ++half) {
        int i0 = tid + half * 4 * LOSS_TOTAL;
        float4 a[4], b[4];
        unsigned mw[4];
        #pragma unroll
        for (int k = 0; k < 4; ++k) {
            int i = i0 + k * LOSS_TOTAL;
            a[k]  = __ldcs(inp + i);
            b[k]  = __ldcs(tgt + i);
            mw[k] = g_mask[i >> 3];
        }
        #pragma unroll
        for (int k = 0; k < 4; ++k) {
            unsigned bits = mw[k] >> shift;
            float w0 = 1.0f + PW * (float)((bits >> 0) & 1u);
            float w1 = 1.0f + PW * (float)((bits >> 1) & 1u);
            float w2 = 1.0f + PW * (float)((bits >> 2) & 1u);
            float w3 = 1.0f + PW * (float)((bits >> 3) & 1u);
            lsum += fabsf(b[k].x - a[k].x) * w0;
            lsum += fabsf(b[k].y - a[k].y) * w1;
            lsum += fabsf(b[k].z - a[k].z) * w2;
            lsum += fabsf(b[k].w - a[k].w) * w3;
        }
    }

    // warp reduce
    #pragma unroll
    for (int off = 16; off > 0; off >>= 1)
        lsum += __shfl_down_sync(0xFFFFFFFFu, lsum, off);

    __shared__ float warp_sums[LOSS_THREADS / 32];
    int lane = threadIdx.x & 31;
    int wid  = threadIdx.x >> 5;
    if (lane == 0) warp_sums[wid] = lsum;
    __syncthreads();

    if (wid == 0) {
        float s = (lane < LOSS_THREADS / 32) ? warp_sums[lane] : 0.0f;
        #pragma unroll
        for (int off = 4; off > 0; off >>= 1)
            s += __shfl_down_sync(0xFFFFFFFFu, s, off);
        if (lane == 0) {
            atomicAdd(&g_acc, (double)s);
            __threadfence();
            unsigned prev = atomicAdd(&g_bcount, 1u);
            if (prev == gridDim.x - 1) {
                out[0] = (float)(g_acc / (double)NB);
                g_acc = 0.0;          // reset for next graph replay
                g_bcount = 0u;
            }
        }
    }
}

extern "C" void kernel_launch(void* const* d_in, const int* in_sizes, int n_in,
                              void* d_out, int out_size) {
    const float* inp = (const float*)d_in[0];
    const float* tgt = (const float*)d_in[1];
    float* out = (float*)d_out;

    mask_pack_kernel<<<NB / 4 / 256, 256>>>(tgt);
    dilate_xy_kernel<<<(NWORDS / 4) / 256, 256>>>();
    dilate_z_kernel<<<(NWORDS / 4) / 256, 256>>>();
    loss_kernel<<<LOSS_BLOCKS, LOSS_THREADS>>>((const float4*)inp,
                                               (const float4*)tgt, out);
}

// round 3
// speedup vs baseline: 1.7799x; 1.0593x over previous
#include <cuda_runtime.h>
#include <cuda_fp8.h>
#include <cuda_fp16.h>
#include <cstdint>

// Problem constants (B=2, C=1, D=128, H=256, W=256)
#define NVOL   2
#define DD     128
#define HH     256
#define WW     256
#define NB     (NVOL*DD*HH*WW)      // 16,777,216 voxels
#define WPR    (WW/32)              // 8 packed words per row
#define NWORDS (NVOL*DD*HH*WPR)     // 524,288 words (2 MB)
#define NQ     (NB/4)               // 4,194,304 quads
#define PW     10.0f

#define P1_BLOCKS  512
#define P1_THREADS 512
#define P1_TOTAL   (P1_BLOCKS*P1_THREADS)   // 262,144 -> 16 quads/thread

#define P2_BLOCKS  512
#define P2_THREADS 512
#define P2_TOTAL   (P2_BLOCKS*P2_THREADS)   // 262,144 -> 2 words/thread

// Scratch (allocation-free __device__ globals; zero-initialized at load)
__device__ unsigned int g_mask[NWORDS];
__device__ unsigned int g_tmp[NWORDS];
__device__ unsigned int g_diff[NQ];        // 4 x fp8(e4m3) |t-i| per quad, 16 MB
__device__ double g_base;
__device__ double g_extra;
__device__ unsigned int g_bcount;

// ---------------------------------------------------------------------------
// Pass 1: read input+target once. Emits:
//   - base = sum |t-i| over everything (double atomic per block)
//   - packed support mask (0 < t < 1), 1 bit/voxel
//   - per-voxel |t-i| as fp8 e4m3 (unbiased RN; error on sum ~1e-5 rel)
// ---------------------------------------------------------------------------
__global__ void __launch_bounds__(P1_THREADS) pass1_kernel(
        const float4* __restrict__ inp,
        const float4* __restrict__ tgt) {
    int tid = blockIdx.x * blockDim.x + threadIdx.x;
    float base = 0.0f;

    #pragma unroll
    for (int g = 0; g < 4; ++g) {
        float4 a[4], b[4];
        int i0 = tid + g * 4 * P1_TOTAL;
        #pragma unroll
        for (int k = 0; k < 4; ++k) {
            int i = i0 + k * P1_TOTAL;
            a[k] = __ldcs(inp + i);
            b[k] = __ldcs(tgt + i);
        }
        #pragma unroll
        for (int k = 0; k < 4; ++k) {
            int i = i0 + k * P1_TOTAL;
            float dx = fabsf(b[k].x - a[k].x);
            float dy = fabsf(b[k].y - a[k].y);
            float dz = fabsf(b[k].z - a[k].z);
            float dw = fabsf(b[k].w - a[k].w);
            base += (dx + dy) + (dz + dw);

            unsigned lo = (unsigned)__nv_cvt_float2_to_fp8x2(
                make_float2(dx, dy), __NV_SATFINITE, __NV_E4M3);
            unsigned hi = (unsigned)__nv_cvt_float2_to_fp8x2(
                make_float2(dz, dw), __NV_SATFINITE, __NV_E4M3);
            g_diff[i] = lo | (hi << 16);

            unsigned nib =
                (unsigned)(b[k].x > 0.0f && b[k].x < 1.0f)
              | ((unsigned)(b[k].y > 0.0f && b[k].y < 1.0f) << 1)
              | ((unsigned)(b[k].z > 0.0f && b[k].z < 1.0f) << 2)
              | ((unsigned)(b[k].w > 0.0f && b[k].w < 1.0f) << 3);
            // 8 consecutive threads' nibbles -> one 32-bit word
            unsigned p  = nib | (__shfl_down_sync(0xFFFFFFFFu, nib, 1) << 4);
            unsigned p2 = p   | (__shfl_down_sync(0xFFFFFFFFu, p,   2) << 8);
            unsigned w  = p2  | (__shfl_down_sync(0xFFFFFFFFu, p2,  4) << 16);
            if ((threadIdx.x & 7) == 0) g_mask[i >> 3] = w;
        }
    }

    #pragma unroll
    for (int off = 16; off > 0; off >>= 1)
        base += __shfl_down_sync(0xFFFFFFFFu, base, off);
    __shared__ float ws[P1_THREADS / 32];
    int lane = threadIdx.x & 31, wid = threadIdx.x >> 5;
    if (lane == 0) ws[wid] = base;
    __syncthreads();
    if (wid == 0) {
        float s = (lane < P1_THREADS / 32) ? ws[lane] : 0.0f;
        #pragma unroll
        for (int off = 8; off > 0; off >>= 1)
            s += __shfl_down_sync(0xFFFFFFFFu, s, off);
        if (lane == 0) atomicAdd(&g_base, (double)s);
    }
}

// horizontal (x) dilation by +-3 bits across word boundaries
__device__ __forceinline__ unsigned hdil3(unsigned prev, unsigned cur, unsigned next) {
    unsigned r = cur;
    r |= (cur << 1) | (prev >> 31);
    r |= (cur << 2) | (prev >> 30);
    r |= (cur << 3) | (prev >> 29);
    r |= (cur >> 1) | (next << 31);
    r |= (cur >> 2) | (next << 30);
    r |= (cur >> 3) | (next << 29);
    return r;
}

// ---------------------------------------------------------------------------
// x+y dilation, 4 y-outputs per thread. g_mask -> g_tmp.
// ---------------------------------------------------------------------------
__global__ void dilate_xy_kernel() {
    int t = blockIdx.x * blockDim.x + threadIdx.x;    // 131072 threads
    int wx = t & 7;
    int yg = (t >> 3) & 63;
    int vz = t >> 9;                                  // v*DD+z, 0..255
    int rowbase = vz << 11;
    int y0 = yg << 2;

    unsigned hr[10];
    #pragma unroll
    for (int r = 0; r < 10; ++r) {
        int yy = y0 - 3 + r;
        if (yy < 0 || yy >= HH) { hr[r] = 0u; continue; }
        int base = rowbase + (yy << 3);
        unsigned cur  = g_mask[base + wx];
        unsigned prev = (wx > 0) ? g_mask[base + wx - 1] : 0u;
        unsigned next = (wx < 7) ? g_mask[base + wx + 1] : 0u;
        hr[r] = hdil3(prev, cur, next);
    }
    #pragma unroll
    for (int k = 0; k < 4; ++k) {
        unsigned acc = hr[k];
        #pragma unroll
        for (int r = 1; r < 7; ++r) acc |= hr[k + r];
        g_tmp[rowbase + ((y0 + k) << 3) + wx] = acc;
    }
}

// ---------------------------------------------------------------------------
// z dilation, 4 z-outputs per thread. g_tmp -> g_mask (dilated result).
// ---------------------------------------------------------------------------
__global__ void dilate_z_kernel() {
    int t = blockIdx.x * blockDim.x + threadIdx.x;    // 131072 threads
    int wxy = t & 2047;
    int zg  = (t >> 11) & 31;
    int v   = t >> 16;
    int z0  = zg << 2;

    unsigned c[10];
    #pragma unroll
    for (int r = 0; r < 10; ++r) {
        int zz = z0 - 3 + r;
        c[r] = (zz >= 0 && zz < DD) ? g_tmp[(((v << 7) + zz) << 11) + wxy] : 0u;
    }
    #pragma unroll
    for (int k = 0; k < 4; ++k) {
        unsigned acc = c[k];
        #pragma unroll
        for (int r = 1; r < 7; ++r) acc |= c[k + r];
        g_mask[(((v << 7) + (z0 + k)) << 11) + wxy] = acc;
    }
}

// expand 4 mask bits into a 4-byte lane mask
__device__ __forceinline__ unsigned nib2bytes(unsigned bits) {
    return ((bits & 1u)        * 0x000000FFu)
         | (((bits >> 1) & 1u) * 0x0000FF00u)
         | (((bits >> 2) & 1u) * 0x00FF0000u)
         | (((bits >> 3) & 1u) * 0xFF000000u);
}

__device__ __forceinline__ float sum_fp8x4(unsigned w) {
    __half2_raw h0 = __nv_cvt_fp8x2_to_halfraw2(
        (__nv_fp8x2_storage_t)(w & 0xFFFFu), __NV_E4M3);
    __half2_raw h1 = __nv_cvt_fp8x2_to_halfraw2(
        (__nv_fp8x2_storage_t)(w >> 16), __NV_E4M3);
    float2 f0 = __half22float2(*(__half2*)&h0);
    float2 f1 = __half22float2(*(__half2*)&h1);
    return (f0.x + f0.y) + (f1.x + f1.y);
}

// ---------------------------------------------------------------------------
// Pass 2: extra = sum of fp8 diffs over dilated-mask voxels (L2-resident),
// then finalize: out = (base + 10*extra)/NB in the last block.
// ---------------------------------------------------------------------------
__global__ void __launch_bounds__(P2_THREADS) pass2_kernel(float* __restrict__ out) {
    int tid = blockIdx.x * blockDim.x + threadIdx.x;
    float extra = 0.0f;

    #pragma unroll
    for (int g = 0; g < 2; ++g) {
        int W = tid + g * P2_TOTAL;                 // word index
        unsigned mw = g_mask[W];
        if (mw != 0u) {
            const uint4* dptr = (const uint4*)&g_diff[W << 3];
            uint4 d0 = dptr[0];
            uint4 d1 = dptr[1];
            extra += sum_fp8x4(d0.x & nib2bytes(mw >> 0));
            extra += sum_fp8x4(d0.y & nib2bytes(mw >> 4));
            extra += sum_fp8x4(d0.z & nib2bytes(mw >> 8));
            extra += sum_fp8x4(d0.w & nib2bytes(mw >> 12));
            extra += sum_fp8x4(d1.x & nib2bytes(mw >> 16));
            extra += sum_fp8x4(d1.y & nib2bytes(mw >> 20));
            extra += sum_fp8x4(d1.z & nib2bytes(mw >> 24));
            extra += sum_fp8x4(d1.w & nib2bytes(mw >> 28));
        }
    }

    #pragma unroll
    for (int off = 16; off > 0; off >>= 1)
        extra += __shfl_down_sync(0xFFFFFFFFu, extra, off);
    __shared__ float ws[P2_THREADS / 32];
    int lane = threadIdx.x & 31, wid = threadIdx.x >> 5;
    if (lane == 0) ws[wid] = extra;
    __syncthreads();
    if (wid == 0) {
        float s = (lane < P2_THREADS / 32) ? ws[lane] : 0.0f;
        #pragma unroll
        for (int off = 8; off > 0; off >>= 1)
            s += __shfl_down_sync(0xFFFFFFFFu, s, off);
        if (lane == 0) {
            atomicAdd(&g_extra, (double)s);
            __threadfence();
            unsigned prev = atomicAdd(&g_bcount, 1u);
            if (prev == gridDim.x - 1) {
                out[0] = (float)((g_base + (double)PW * g_extra) / (double)NB);
                g_base = 0.0;        // reset for next graph replay
                g_extra = 0.0;
                g_bcount = 0u;
            }
        }
    }
}

extern "C" void kernel_launch(void* const* d_in, const int* in_sizes, int n_in,
                              void* d_out, int out_size) {
    const float* inp = (const float*)d_in[0];
    const float* tgt = (const float*)d_in[1];
    float* out = (float*)d_out;

    pass1_kernel<<<P1_BLOCKS, P1_THREADS>>>((const float4*)inp, (const float4*)tgt);
    dilate_xy_kernel<<<(NWORDS / 4) / 256, 256>>>();
    dilate_z_kernel<<<(NWORDS / 4) / 256, 256>>>();
    pass2_kernel<<<P2_BLOCKS, P2_THREADS>>>(out);
}

// round 4
// speedup vs baseline: 2.0082x; 1.1283x over previous
#include <cuda_runtime.h>
#include <cstdint>

// Problem constants (B=2, C=1, D=128, H=256, W=256)
#define NVOL   2
#define DD     128
#define HH     256
#define WW     256
#define NB     (NVOL*DD*HH*WW)      // 16,777,216 voxels
#define WPR    (WW/32)              // 8 packed words per row
#define NWORDS (NVOL*DD*HH*WPR)     // 524,288 words (2 MB)
#define PW     10.0

#define P1_BLOCKS  512
#define P1_THREADS 512
#define P1_TOTAL   (P1_BLOCKS*P1_THREADS)   // 262,144 -> 16 quads/thread

#define P2_BLOCKS  256
#define P2_THREADS 512
#define P2_TOTAL   (P2_BLOCKS*P2_THREADS)   // 131,072 -> 4 words/thread

// Scratch (allocation-free __device__ globals; zero-initialized at load)
__device__ unsigned int g_mask[NWORDS];
__device__ unsigned int g_tmp[NWORDS];
__device__ double g_base;      // sum |t-i| over all voxels
__device__ double g_corr;      // sum |t-i| over NOT-dilated voxels
__device__ unsigned int g_bcount;

// ---------------------------------------------------------------------------
// Pass 1: single streaming read of input+target (128 MB).
// Emits base = sum|t-i| (exact fp32->double) and packed support mask.
// ---------------------------------------------------------------------------
__global__ void __launch_bounds__(P1_THREADS) pass1_kernel(
        const float4* __restrict__ inp,
        const float4* __restrict__ tgt) {
    int tid = blockIdx.x * blockDim.x + threadIdx.x;
    float base = 0.0f;

    #pragma unroll
    for (int g = 0; g < 4; ++g) {
        float4 a[4], b[4];
        int i0 = tid + g * 4 * P1_TOTAL;
        #pragma unroll
        for (int k = 0; k < 4; ++k) {
            int i = i0 + k * P1_TOTAL;
            a[k] = __ldcs(inp + i);
            b[k] = __ldcs(tgt + i);
        }
        #pragma unroll
        for (int k = 0; k < 4; ++k) {
            int i = i0 + k * P1_TOTAL;
            float dx = fabsf(b[k].x - a[k].x);
            float dy = fabsf(b[k].y - a[k].y);
            float dz = fabsf(b[k].z - a[k].z);
            float dw = fabsf(b[k].w - a[k].w);
            base += (dx + dy) + (dz + dw);

            unsigned nib =
                (unsigned)(b[k].x > 0.0f && b[k].x < 1.0f)
              | ((unsigned)(b[k].y > 0.0f && b[k].y < 1.0f) << 1)
              | ((unsigned)(b[k].z > 0.0f && b[k].z < 1.0f) << 2)
              | ((unsigned)(b[k].w > 0.0f && b[k].w < 1.0f) << 3);
            // 8 consecutive threads' nibbles -> one 32-bit word
            unsigned p  = nib | (__shfl_down_sync(0xFFFFFFFFu, nib, 1) << 4);
            unsigned p2 = p   | (__shfl_down_sync(0xFFFFFFFFu, p,   2) << 8);
            unsigned w  = p2  | (__shfl_down_sync(0xFFFFFFFFu, p2,  4) << 16);
            if ((threadIdx.x & 7) == 0) g_mask[i >> 3] = w;
        }
    }

    #pragma unroll
    for (int off = 16; off > 0; off >>= 1)
        base += __shfl_down_sync(0xFFFFFFFFu, base, off);
    __shared__ float ws[P1_THREADS / 32];
    int lane = threadIdx.x & 31, wid = threadIdx.x >> 5;
    if (lane == 0) ws[wid] = base;
    __syncthreads();
    if (wid == 0) {
        float s = (lane < P1_THREADS / 32) ? ws[lane] : 0.0f;
        #pragma unroll
        for (int off = 8; off > 0; off >>= 1)
            s += __shfl_down_sync(0xFFFFFFFFu, s, off);
        if (lane == 0) atomicAdd(&g_base, (double)s);
    }
}

// horizontal (x) dilation by +-3 bits across word boundaries
__device__ __forceinline__ unsigned hdil3(unsigned prev, unsigned cur, unsigned next) {
    unsigned r = cur;
    r |= (cur << 1) | (prev >> 31);
    r |= (cur << 2) | (prev >> 30);
    r |= (cur << 3) | (prev >> 29);
    r |= (cur >> 1) | (next << 31);
    r |= (cur >> 2) | (next << 30);
    r |= (cur >> 3) | (next << 29);
    return r;
}

// ---------------------------------------------------------------------------
// x+y dilation, 4 y-outputs per thread. g_mask -> g_tmp.
// ---------------------------------------------------------------------------
__global__ void dilate_xy_kernel() {
    int t = blockIdx.x * blockDim.x + threadIdx.x;    // 131072 threads
    int wx = t & 7;
    int yg = (t >> 3) & 63;
    int vz = t >> 9;                                  // v*DD+z, 0..255
    int rowbase = vz << 11;
    int y0 = yg << 2;

    unsigned hr[10];
    #pragma unroll
    for (int r = 0; r < 10; ++r) {
        int yy = y0 - 3 + r;
        if (yy < 0 || yy >= HH) { hr[r] = 0u; continue; }
        int base = rowbase + (yy << 3);
        unsigned cur  = g_mask[base + wx];
        unsigned prev = (wx > 0) ? g_mask[base + wx - 1] : 0u;
        unsigned next = (wx < 7) ? g_mask[base + wx + 1] : 0u;
        hr[r] = hdil3(prev, cur, next);
    }
    #pragma unroll
    for (int k = 0; k < 4; ++k) {
        unsigned acc = hr[k];
        #pragma unroll
        for (int r = 1; r < 7; ++r) acc |= hr[k + r];
        g_tmp[rowbase + ((y0 + k) << 3) + wx] = acc;
    }
}

// ---------------------------------------------------------------------------
// z dilation, 4 z-outputs per thread. g_tmp -> g_mask (dilated result).
// ---------------------------------------------------------------------------
__global__ void dilate_z_kernel() {
    int t = blockIdx.x * blockDim.x + threadIdx.x;    // 131072 threads
    int wxy = t & 2047;
    int zg  = (t >> 11) & 31;
    int v   = t >> 16;
    int z0  = zg << 2;

    unsigned c[10];
    #pragma unroll
    for (int r = 0; r < 10; ++r) {
        int zz = z0 - 3 + r;
        c[r] = (zz >= 0 && zz < DD) ? g_tmp[(((v << 7) + zz) << 11) + wxy] : 0u;
    }
    #pragma unroll
    for (int k = 0; k < 4; ++k) {
        unsigned acc = c[k];
        #pragma unroll
        for (int r = 1; r < 7; ++r) acc |= c[k + r];
        g_mask[(((v << 7) + (z0 + k)) << 11) + wxy] = acc;
    }
}

// ---------------------------------------------------------------------------
// Pass 2: correction = sum |t-i| over NOT-dilated voxels (rare), then
// finalize: out = (11*base - 10*corr)/NB in the last block.
//   loss = sum |d|*(1+10*m) = 11*sum|d| - 10*sum_{!m}|d|
// ---------------------------------------------------------------------------
__global__ void __launch_bounds__(P2_THREADS) pass2_kernel(
        const float* __restrict__ inp,
        const float* __restrict__ tgt,
        float* __restrict__ out) {
    int tid = blockIdx.x * blockDim.x + threadIdx.x;
    float corr = 0.0f;

    #pragma unroll
    for (int g = 0; g < 4; ++g) {
        int W = tid + g * P2_TOTAL;                 // word index
        unsigned miss = ~g_mask[W];                 // zero bits = unweighted voxels
        while (miss) {
            int bit = __ffs(miss) - 1;
            miss &= miss - 1u;
            int i = (W << 5) + bit;
            corr += fabsf(tgt[i] - inp[i]);
        }
    }

    #pragma unroll
    for (int off = 16; off > 0; off >>= 1)
        corr += __shfl_down_sync(0xFFFFFFFFu, corr, off);
    __shared__ float ws[P2_THREADS / 32];
    int lane = threadIdx.x & 31, wid = threadIdx.x >> 5;
    if (lane == 0) ws[wid] = corr;
    __syncthreads();
    if (wid == 0) {
        float s = (lane < P2_THREADS / 32) ? ws[lane] : 0.0f;
        #pragma unroll
        for (int off = 8; off > 0; off >>= 1)
            s += __shfl_down_sync(0xFFFFFFFFu, s, off);
        if (lane == 0) {
            atomicAdd(&g_corr, (double)s);
            __threadfence();
            unsigned prev = atomicAdd(&g_bcount, 1u);
            if (prev == gridDim.x - 1) {
                double total = (1.0 + PW) * g_base - PW * g_corr;
                out[0] = (float)(total / (double)NB);
                g_base = 0.0;        // reset for next graph replay
                g_corr = 0.0;
                g_bcount = 0u;
            }
        }
    }
}

extern "C" void kernel_launch(void* const* d_in, const int* in_sizes, int n_in,
                              void* d_out, int out_size) {
    const float* inp = (const float*)d_in[0];
    const float* tgt = (const float*)d_in[1];
    float* out = (float*)d_out;

    pass1_kernel<<<P1_BLOCKS, P1_THREADS>>>((const float4*)inp, (const float4*)tgt);
    dilate_xy_kernel<<<(NWORDS / 4) / 256, 256>>>();
    dilate_z_kernel<<<(NWORDS / 4) / 256, 256>>>();
    pass2_kernel<<<P2_BLOCKS, P2_THREADS>>>(inp, tgt, out);
}

// round 5
// speedup vs baseline: 2.0926x; 1.0420x over previous
#include <cuda_runtime.h>
#include <cstdint>

// Problem constants (B=2, C=1, D=128, H=256, W=256)
#define NVOL   2
#define DD     128
#define HH     256
#define WW     256
#define NB     (NVOL*DD*HH*WW)      // 16,777,216 voxels
#define WPR    (WW/32)              // 8 packed words per row
#define NWORDS (NVOL*DD*HH*WPR)     // 524,288 words (2 MB)
#define PW     10.0

#define P1_BLOCKS  512
#define P1_THREADS 512
#define P1_TOTAL   (P1_BLOCKS*P1_THREADS)   // 262,144 -> 16 quads/thread

#define DZ_THREADS 256
#define DZ_BLOCKS  ((NWORDS / 4) / DZ_THREADS)   // 512 blocks

// Scratch (allocation-free __device__ globals; zero-initialized at load)
__device__ unsigned int g_mask[NWORDS];
__device__ unsigned int g_tmp[NWORDS];
__device__ double g_base;      // sum |t-i| over all voxels
__device__ double g_corr;      // sum |t-i| over NOT-dilated voxels
__device__ unsigned int g_bcount;

// ---------------------------------------------------------------------------
// Pass 1: single streaming read of input+target (128 MB).
// Emits base = sum|t-i| and packed support mask (0 < t < 1).
// ---------------------------------------------------------------------------
__global__ void __launch_bounds__(P1_THREADS) pass1_kernel(
        const float4* __restrict__ inp,
        const float4* __restrict__ tgt) {
    int tid = blockIdx.x * blockDim.x + threadIdx.x;
    float base = 0.0f;

    #pragma unroll
    for (int g = 0; g < 4; ++g) {
        float4 a[4], b[4];
        int i0 = tid + g * 4 * P1_TOTAL;
        #pragma unroll
        for (int k = 0; k < 4; ++k) {
            int i = i0 + k * P1_TOTAL;
            a[k] = __ldcs(inp + i);
            b[k] = __ldcs(tgt + i);
        }
        #pragma unroll
        for (int k = 0; k < 4; ++k) {
            int i = i0 + k * P1_TOTAL;
            float dx = fabsf(b[k].x - a[k].x);
            float dy = fabsf(b[k].y - a[k].y);
            float dz = fabsf(b[k].z - a[k].z);
            float dw = fabsf(b[k].w - a[k].w);
            base += (dx + dy) + (dz + dw);

            unsigned nib =
                (unsigned)(b[k].x > 0.0f && b[k].x < 1.0f)
              | ((unsigned)(b[k].y > 0.0f && b[k].y < 1.0f) << 1)
              | ((unsigned)(b[k].z > 0.0f && b[k].z < 1.0f) << 2)
              | ((unsigned)(b[k].w > 0.0f && b[k].w < 1.0f) << 3);
            // 8 consecutive threads' nibbles -> one 32-bit word
            unsigned p  = nib | (__shfl_down_sync(0xFFFFFFFFu, nib, 1) << 4);
            unsigned p2 = p   | (__shfl_down_sync(0xFFFFFFFFu, p,   2) << 8);
            unsigned w  = p2  | (__shfl_down_sync(0xFFFFFFFFu, p2,  4) << 16);
            if ((threadIdx.x & 7) == 0) g_mask[i >> 3] = w;
        }
    }

    #pragma unroll
    for (int off = 16; off > 0; off >>= 1)
        base += __shfl_down_sync(0xFFFFFFFFu, base, off);
    __shared__ float ws[P1_THREADS / 32];
    int lane = threadIdx.x & 31, wid = threadIdx.x >> 5;
    if (lane == 0) ws[wid] = base;
    __syncthreads();
    if (wid == 0) {
        float s = (lane < P1_THREADS / 32) ? ws[lane] : 0.0f;
        #pragma unroll
        for (int off = 8; off > 0; off >>= 1)
            s += __shfl_down_sync(0xFFFFFFFFu, s, off);
        if (lane == 0) atomicAdd(&g_base, (double)s);
    }
}

// horizontal (x) dilation by +-3 bits across word boundaries
__device__ __forceinline__ unsigned hdil3(unsigned prev, unsigned cur, unsigned next) {
    unsigned r = cur;
    r |= (cur << 1) | (prev >> 31);
    r |= (cur << 2) | (prev >> 30);
    r |= (cur << 3) | (prev >> 29);
    r |= (cur >> 1) | (next << 31);
    r |= (cur >> 2) | (next << 30);
    r |= (cur >> 3) | (next << 29);
    return r;
}

// ---------------------------------------------------------------------------
// x+y dilation, 4 y-outputs per thread. g_mask -> g_tmp.
// ---------------------------------------------------------------------------
__global__ void dilate_xy_kernel() {
    int t = blockIdx.x * blockDim.x + threadIdx.x;    // 131072 threads
    int wx = t & 7;
    int yg = (t >> 3) & 63;
    int vz = t >> 9;                                  // v*DD+z, 0..255
    int rowbase = vz << 11;
    int y0 = yg << 2;

    unsigned hr[10];
    #pragma unroll
    for (int r = 0; r < 10; ++r) {
        int yy = y0 - 3 + r;
        if (yy < 0 || yy >= HH) { hr[r] = 0u; continue; }
        int base = rowbase + (yy << 3);
        unsigned cur  = g_mask[base + wx];
        unsigned prev = (wx > 0) ? g_mask[base + wx - 1] : 0u;
        unsigned next = (wx < 7) ? g_mask[base + wx + 1] : 0u;
        hr[r] = hdil3(prev, cur, next);
    }
    #pragma unroll
    for (int k = 0; k < 4; ++k) {
        unsigned acc = hr[k];
        #pragma unroll
        for (int r = 1; r < 7; ++r) acc |= hr[k + r];
        g_tmp[rowbase + ((y0 + k) << 3) + wx] = acc;
    }
}

// ---------------------------------------------------------------------------
// Fused z-dilation + complement correction + finalize.
// For each output word: OR 7 z-neighbors of g_tmp; zero bits of the result
// are the unweighted voxels -> gather their |t-i| directly (rare).
//   loss = 11*base - 10*corr ; out = loss/NB written by the last block.
// ---------------------------------------------------------------------------
__global__ void __launch_bounds__(DZ_THREADS) dilate_z_corr_kernel(
        const float* __restrict__ inp,
        const float* __restrict__ tgt,
        float* __restrict__ out) {
    int t = blockIdx.x * blockDim.x + threadIdx.x;    // 131072 threads
    int wxy = t & 2047;                               // word within z-slice
    int zg  = (t >> 11) & 31;
    int v   = t >> 16;
    int z0  = zg << 2;

    unsigned c[10];
    #pragma unroll
    for (int r = 0; r < 10; ++r) {
        int zz = z0 - 3 + r;
        c[r] = (zz >= 0 && zz < DD) ? g_tmp[(((v << 7) + zz) << 11) + wxy] : 0u;
    }

    float corr = 0.0f;
    #pragma unroll
    for (int k = 0; k < 4; ++k) {
        unsigned acc = c[k];
        #pragma unroll
        for (int r = 1; r < 7; ++r) acc |= c[k + r];
        unsigned miss = ~acc;                         // unweighted voxels
        if (miss) {
            int wordidx = (((v << 7) + (z0 + k)) << 11) + wxy;
            int vox0 = wordidx << 5;
            do {
                int bit = __ffs(miss) - 1;
                miss &= miss - 1u;
                int i = vox0 + bit;
                corr += fabsf(tgt[i] - inp[i]);
            } while (miss);
        }
    }

    #pragma unroll
    for (int off = 16; off > 0; off >>= 1)
        corr += __shfl_down_sync(0xFFFFFFFFu, corr, off);
    __shared__ float ws[DZ_THREADS / 32];
    int lane = threadIdx.x & 31, wid = threadIdx.x >> 5;
    if (lane == 0) ws[wid] = corr;
    __syncthreads();
    if (wid == 0) {
        float s = (lane < DZ_THREADS / 32) ? ws[lane] : 0.0f;
        #pragma unroll
        for (int off = 4; off > 0; off >>= 1)
            s += __shfl_down_sync(0xFFFFFFFFu, s, off);
        if (lane == 0) {
            atomicAdd(&g_corr, (double)s);
            __threadfence();
            unsigned prev = atomicAdd(&g_bcount, 1u);
            if (prev == gridDim.x - 1) {
                double total = (1.0 + PW) * g_base - PW * g_corr;
                out[0] = (float)(total / (double)NB);
                g_base = 0.0;        // reset for next graph replay
                g_corr = 0.0;
                g_bcount = 0u;
            }
        }
    }
}

extern "C" void kernel_launch(void* const* d_in, const int* in_sizes, int n_in,
                              void* d_out, int out_size) {
    const float* inp = (const float*)d_in[0];
    const float* tgt = (const float*)d_in[1];
    float* out = (float*)d_out;

    pass1_kernel<<<P1_BLOCKS, P1_THREADS>>>((const float4*)inp, (const float4*)tgt);
    dilate_xy_kernel<<<(NWORDS / 4) / 256, 256>>>();
    dilate_z_corr_kernel<<<DZ_BLOCKS, DZ_THREADS>>>(inp, tgt, out);
}